// round 2
// baseline (speedup 1.0000x reference)
#include <cuda_runtime.h>
#include <math.h>

#define BB 4
#define NB 288
#define NC 32
#define NP 16
#define HW 196
#define Q  28      // hw elements per route block
#define QV 7       // float4s per route block hw chunk
#define EPSF 1e-5f

#define NVPHW (BB*NC*NP*HW)   // 401408
#define NCHW  (BB*NC*HW)      // 25088
#define NCHW4 (NCHW/4)        // 6272

// scratch (allocation-free: __device__ globals)
__device__ float    g_s[NVPHW];
__device__ float    g_v[NVPHW];
__device__ unsigned g_maxb[NCHW];
__device__ unsigned g_minb[NCHW];
__device__ float    g_inv[NCHW];

// ---------------------------------------------------------------------------
__global__ void k_init() {
    int i = blockIdx.x * blockDim.x + threadIdx.x;
    if (i < NCHW) { g_maxb[i] = 0u; g_minb[i] = 0x7F800000u; }
    if (i < NVPHW) g_s[i] = 0.0f;
}

// ---------------------------------------------------------------------------
// Pass A: pose norms -> max/min over B (register-accumulated, one atomic set
// per thread), and s0_raw = sum_B u (register-accumulated, REDG flush).
// grid (18 Bgroups of 16, 4 c-groups of 8, 4 b), 392 threads = (csub 0..7, q4 0..48)
__global__ void __launch_bounds__(392, 1) k_passA(const float* __restrict__ u) {
    int bg = blockIdx.x;          // 0..17
    int cg = blockIdx.y;          // 0..3
    int b  = blockIdx.z;          // 0..3
    int tid = threadIdx.x;
    int csub = tid / 49;          // 0..7
    int q4   = tid % 49;          // 0..48
    int c = cg * 8 + csub;
    int hwoff = q4 * 4;

    float4 sacc[NP];
#pragma unroll
    for (int p = 0; p < NP; p++) sacc[p] = make_float4(0.f, 0.f, 0.f, 0.f);
    float4 mx = make_float4(-1e30f, -1e30f, -1e30f, -1e30f);
    float4 mn = make_float4( 1e30f,  1e30f,  1e30f,  1e30f);

    for (int bi = 0; bi < 16; bi++) {
        int Bidx = bg * 16 + bi;
        const float* up = u + (((size_t)(b * NB + Bidx) * NC + c) * NP) * HW + hwoff;
        float4 n2 = make_float4(EPSF, EPSF, EPSF, EPSF);
#pragma unroll
        for (int p = 0; p < NP; p++) {
            float4 x = *(const float4*)(up + p * HW);
            sacc[p].x += x.x; sacc[p].y += x.y; sacc[p].z += x.z; sacc[p].w += x.w;
            n2.x += x.x * x.x; n2.y += x.y * x.y; n2.z += x.z * x.z; n2.w += x.w * x.w;
        }
        float4 nb = make_float4(sqrtf(n2.x), sqrtf(n2.y), sqrtf(n2.z), sqrtf(n2.w));
        mx.x = fmaxf(mx.x, nb.x); mx.y = fmaxf(mx.y, nb.y);
        mx.z = fmaxf(mx.z, nb.z); mx.w = fmaxf(mx.w, nb.w);
        mn.x = fminf(mn.x, nb.x); mn.y = fminf(mn.y, nb.y);
        mn.z = fminf(mn.z, nb.z); mn.w = fminf(mn.w, nb.w);
    }

    int mi = (b * NC + c) * HW + hwoff;
    atomicMax(&g_maxb[mi + 0], __float_as_uint(mx.x));
    atomicMax(&g_maxb[mi + 1], __float_as_uint(mx.y));
    atomicMax(&g_maxb[mi + 2], __float_as_uint(mx.z));
    atomicMax(&g_maxb[mi + 3], __float_as_uint(mx.w));
    atomicMin(&g_minb[mi + 0], __float_as_uint(mn.x));
    atomicMin(&g_minb[mi + 1], __float_as_uint(mn.y));
    atomicMin(&g_minb[mi + 2], __float_as_uint(mn.z));
    atomicMin(&g_minb[mi + 3], __float_as_uint(mn.w));

    int sbase = ((b * NC + c) * NP) * HW + hwoff;
#pragma unroll
    for (int p = 0; p < NP; p++) {
        atomicAdd(&g_s[sbase + p * HW + 0], sacc[p].x);
        atomicAdd(&g_s[sbase + p * HW + 1], sacc[p].y);
        atomicAdd(&g_s[sbase + p * HW + 2], sacc[p].z);
        atomicAdd(&g_s[sbase + p * HW + 3], sacc[p].w);
    }
}

// ---------------------------------------------------------------------------
// squash: one thread per (b,C,hw4)
// mode 0: compute inv, scale=inv/32, g_v  = squash, zero g_s
// mode 1: scale=inv,                 g_v += squash, zero g_s   (v0+v1 trick)
// mode 2: scale=inv,                 write v + a_out to output
__global__ void k_squash(float* __restrict__ vout, float* __restrict__ aout, int mode) {
    int i = blockIdx.x * blockDim.x + threadIdx.x;
    if (i >= NCHW4) return;
    int bc = i / 49, q4 = i % 49;
    int mi = bc * HW + q4 * 4;

    float inv[4];
    if (mode == 0) {
#pragma unroll
        for (int j = 0; j < 4; j++) {
            float mxv = __uint_as_float(g_maxb[mi + j]);
            float mnv = __uint_as_float(g_minb[mi + j]);
            inv[j] = 1.0f / (mxv - mnv);
            g_inv[mi + j] = inv[j];
        }
    } else {
        float4 iv = *(const float4*)&g_inv[mi];
        inv[0] = iv.x; inv[1] = iv.y; inv[2] = iv.z; inv[3] = iv.w;
    }
    float mul = (mode == 0) ? (1.0f / 32.0f) : 1.0f;
    float sc[4];
#pragma unroll
    for (int j = 0; j < 4; j++) sc[j] = inv[j] * mul;

    int sbase = bc * NP * HW + q4 * 4;
    float sv[NP][4];
    float n2[4] = {EPSF, EPSF, EPSF, EPSF};
#pragma unroll
    for (int p = 0; p < NP; p++) {
        float4 x = *(const float4*)&g_s[sbase + p * HW];
        float xs[4] = {x.x * sc[0], x.y * sc[1], x.z * sc[2], x.w * sc[3]};
#pragma unroll
        for (int j = 0; j < 4; j++) { sv[p][j] = xs[j]; n2[j] += xs[j] * xs[j]; }
    }
    float f[4];
#pragma unroll
    for (int j = 0; j < 4; j++) f[j] = 1.0f / (1.0f + sqrtf(n2[j]));

    if (mode < 2) {
#pragma unroll
        for (int p = 0; p < NP; p++) {
            float4 vold = make_float4(0.f, 0.f, 0.f, 0.f);
            if (mode == 1) vold = *(const float4*)&g_v[sbase + p * HW];
            float4 vn;
            vn.x = vold.x + sv[p][0] * f[0];
            vn.y = vold.y + sv[p][1] * f[1];
            vn.z = vold.z + sv[p][2] * f[2];
            vn.w = vold.w + sv[p][3] * f[3];
            *(float4*)&g_v[sbase + p * HW] = vn;
            *(float4*)&g_s[sbase + p * HW] = make_float4(0.f, 0.f, 0.f, 0.f);
        }
    } else {
        float av2[4] = {EPSF, EPSF, EPSF, EPSF};
#pragma unroll
        for (int p = 0; p < NP; p++) {
            float4 vn;
            vn.x = sv[p][0] * f[0]; vn.y = sv[p][1] * f[1];
            vn.z = sv[p][2] * f[2]; vn.w = sv[p][3] * f[3];
            *(float4*)&vout[sbase + p * HW] = vn;
            av2[0] += vn.x * vn.x; av2[1] += vn.y * vn.y;
            av2[2] += vn.z * vn.z; av2[3] += vn.w * vn.w;
        }
#pragma unroll
        for (int j = 0; j < 4; j++) aout[mi + j] = sqrtf(av2[j]);
    }
}

// ---------------------------------------------------------------------------
// Routing pass. grid (9 Bgroups of 32, 7 hw-chunks of 28, 4 b), 448 threads.
// thread = (c 0..31, ph 0..1, q4 0..6): owns 1 C x 8 P x 4 hw.
// u kept in registers across softmax (single DRAM read per element!),
// s accumulated in registers, flushed via REDG at block end.
// smem floats: v[512*28] + pr[64*28] + r[32*28] + e[32*28] + inv[32*28]
#define RT 448
extern __shared__ float sh[];

__global__ void __launch_bounds__(RT, 1) k_route(const float* __restrict__ u) {
    float* v_sh   = sh;                 // 14336  layout [pabs][c][hw]
    float* pr_sh  = v_sh + 512 * Q;     // 1792
    float* r_sh   = pr_sh + 64 * Q;     // 896
    float* e_sh   = r_sh + NC * Q;      // 896
    float* inv_sh = e_sh + NC * Q;      // 896

    int bg = blockIdx.x;   // 0..8
    int hq = blockIdx.y;   // 0..6
    int b  = blockIdx.z;   // 0..3
    int tid = threadIdx.x;
    int q4 = tid % QV;            // 0..6
    int ph = (tid / QV) & 1;      // 0..1
    int c  = tid / (2 * QV);      // 0..31
    int hw0 = hq * Q;
    int hwoff = hw0 + q4 * 4;

    // load v slice ([pabs][c][hw] layout) and inv slice
    for (int e = tid; e < 512 * QV; e += RT) {
        int row = e / QV, qq = e % QV;          // row = pabs*32 + c
        int cc = row & 31, pabs = row >> 5;
        float4 val = *(const float4*)&g_v[((b * NC + cc) * NP + pabs) * HW + hw0 + qq * 4];
        *(float4*)&v_sh[row * Q + qq * 4] = val;
    }
    for (int e = tid; e < NC * QV; e += RT) {
        int cc = e / QV, qq = e % QV;
        *(float4*)&inv_sh[cc * Q + qq * 4] =
            *(const float4*)&g_inv[(b * NC + cc) * HW + hw0 + qq * 4];
    }
    __syncthreads();

    float4 invv = *(float4*)&inv_sh[c * Q + q4 * 4];
    float4 acc[8];
#pragma unroll
    for (int p = 0; p < 8; p++) acc[p] = make_float4(0.f, 0.f, 0.f, 0.f);

    const float* ub = u + ((((size_t)b * NB + (size_t)bg * 32) * NC + c) * NP + ph * 8) * HW + hwoff;

    for (int bi = 0; bi < 32; bi++) {
        const float* up = ub + (size_t)bi * (NC * NP * HW);
        float4 uu[8];
#pragma unroll
        for (int p = 0; p < 8; p++) uu[p] = *(const float4*)(up + p * HW);

        // phase 1: partial agreement over this thread's 8 P
        float4 part = make_float4(0.f, 0.f, 0.f, 0.f);
#pragma unroll
        for (int p = 0; p < 8; p++) {
            float4 vv = *(float4*)&v_sh[((ph * 8 + p) * NC + c) * Q + q4 * 4];
            part.x += uu[p].x * vv.x; part.y += uu[p].y * vv.y;
            part.z += uu[p].z * vv.z; part.w += uu[p].w * vv.w;
        }
        *(float4*)&pr_sh[(c * 2 + ph) * Q + q4 * 4] = part;
        __syncthreads();

        float4 pa = *(float4*)&pr_sh[(c * 2 + 0) * Q + q4 * 4];
        float4 pb = *(float4*)&pr_sh[(c * 2 + 1) * Q + q4 * 4];
        float4 r;
        r.x = (pa.x + pb.x) * invv.x; r.y = (pa.y + pb.y) * invv.y;
        r.z = (pa.z + pb.z) * invv.z; r.w = (pa.w + pb.w) * invv.w;
        if (ph == 0) *(float4*)&r_sh[c * Q + q4 * 4] = r;
        __syncthreads();

        // softmax over C
        float4 m = make_float4(-1e30f, -1e30f, -1e30f, -1e30f);
#pragma unroll
        for (int c2 = 0; c2 < NC; c2++) {
            float4 rr = *(float4*)&r_sh[c2 * Q + q4 * 4];
            m.x = fmaxf(m.x, rr.x); m.y = fmaxf(m.y, rr.y);
            m.z = fmaxf(m.z, rr.z); m.w = fmaxf(m.w, rr.w);
        }
        float4 ev;
        ev.x = __expf(r.x - m.x); ev.y = __expf(r.y - m.y);
        ev.z = __expf(r.z - m.z); ev.w = __expf(r.w - m.w);
        if (ph == 0) *(float4*)&e_sh[c * Q + q4 * 4] = ev;
        __syncthreads();

        float4 ssum = make_float4(0.f, 0.f, 0.f, 0.f);
#pragma unroll
        for (int c2 = 0; c2 < NC; c2++) {
            float4 ee = *(float4*)&e_sh[c2 * Q + q4 * 4];
            ssum.x += ee.x; ssum.y += ee.y; ssum.z += ee.z; ssum.w += ee.w;
        }
        float4 cv;
        cv.x = ev.x * (1.0f / ssum.x); cv.y = ev.y * (1.0f / ssum.y);
        cv.z = ev.z * (1.0f / ssum.z); cv.w = ev.w * (1.0f / ssum.w);

        // phase 2: s += c * u   (u still in registers!)
#pragma unroll
        for (int p = 0; p < 8; p++) {
            acc[p].x += cv.x * uu[p].x; acc[p].y += cv.y * uu[p].y;
            acc[p].z += cv.z * uu[p].z; acc[p].w += cv.w * uu[p].w;
        }
    }

    // flush register accumulators
    int sbase = ((b * NC + c) * NP + ph * 8) * HW + hwoff;
#pragma unroll
    for (int p = 0; p < 8; p++) {
        atomicAdd(&g_s[sbase + p * HW + 0], acc[p].x);
        atomicAdd(&g_s[sbase + p * HW + 1], acc[p].y);
        atomicAdd(&g_s[sbase + p * HW + 2], acc[p].z);
        atomicAdd(&g_s[sbase + p * HW + 3], acc[p].w);
    }
}

// ---------------------------------------------------------------------------
extern "C" void kernel_launch(void* const* d_in, const int* in_sizes, int n_in,
                              void* d_out, int out_size) {
    const float* u = (const float*)d_in[0];   // (4,288,32,16,14,14)
    float* out  = (float*)d_out;
    float* vout = out;                        // (4,32,16,14,14)
    float* aout = out + NVPHW;                // (4,32,14,14)

    const int shbytes = (512 * Q + 64 * Q + 3 * NC * Q) * sizeof(float); // 75264
    cudaFuncSetAttribute(k_route, cudaFuncAttributeMaxDynamicSharedMemorySize, shbytes);

    k_init<<<(NVPHW + 255) / 256, 256>>>();
    k_passA<<<dim3(18, 4, 4), 392>>>(u);
    k_squash<<<(NCHW4 + 255) / 256, 256>>>(nullptr, nullptr, 0);  // v0 = squash(s0)
    k_route<<<dim3(9, QV, 4), RT, shbytes>>>(u);                  // r1 -> s1 (uses v0)
    k_squash<<<(NCHW4 + 255) / 256, 256>>>(nullptr, nullptr, 1);  // g_v = v0+v1
    k_route<<<dim3(9, QV, 4), RT, shbytes>>>(u);                  // r2 -> s2 (uses v0+v1)
    k_squash<<<(NCHW4 + 255) / 256, 256>>>(vout, aout, 2);        // v2, a_out
}

// round 3
// speedup vs baseline: 2.5627x; 2.5627x over previous
#include <cuda_runtime.h>
#include <math.h>

#define BB 4
#define NB 288
#define NC 32
#define NP 16
#define HW 196
#define EPSF 1e-5f
#define VS 60          // v_sh row stride (floats), conflict-avoiding pad

#define NVPHW (BB*NC*NP*HW)   // 401408
#define NCHW  (BB*NC*HW)      // 25088
#define NCHW4 (NCHW/4)        // 6272

// scratch (allocation-free: __device__ globals)
__device__ float    g_s[NVPHW];
__device__ float    g_v[NVPHW];
__device__ unsigned g_maxb[NCHW];
__device__ unsigned g_minb[NCHW];
__device__ float    g_inv[NCHW];

// ---------------------------------------------------------------------------
__global__ void k_init() {
    int i = blockIdx.x * blockDim.x + threadIdx.x;
    if (i < NCHW) { g_maxb[i] = 0u; g_minb[i] = 0x7F800000u; }
    if (i < NVPHW) g_s[i] = 0.0f;
}

// ---------------------------------------------------------------------------
// Pass A: pose norms -> max/min over B; s0_raw = sum_B u.
// grid (9 Bgroups of 32, 4 c-groups of 8, 4 b), 392 threads = (csub, q4)
__global__ void __launch_bounds__(392, 1) k_passA(const float* __restrict__ u) {
    int bg = blockIdx.x;          // 0..8
    int cg = blockIdx.y;          // 0..3
    int b  = blockIdx.z;          // 0..3
    int tid = threadIdx.x;
    int csub = tid / 49;          // 0..7
    int q4   = tid % 49;          // 0..48
    int c = cg * 8 + csub;
    int hwoff = q4 * 4;

    float4 sacc[NP];
#pragma unroll
    for (int p = 0; p < NP; p++) sacc[p] = make_float4(0.f, 0.f, 0.f, 0.f);
    float4 mx = make_float4(-1e30f, -1e30f, -1e30f, -1e30f);
    float4 mn = make_float4( 1e30f,  1e30f,  1e30f,  1e30f);

    for (int bi = 0; bi < 32; bi++) {
        int Bidx = bg * 32 + bi;
        const float* up = u + (((size_t)(b * NB + Bidx) * NC + c) * NP) * HW + hwoff;
        float4 n2 = make_float4(EPSF, EPSF, EPSF, EPSF);
#pragma unroll
        for (int p = 0; p < NP; p++) {
            float4 x = *(const float4*)(up + p * HW);
            sacc[p].x += x.x; sacc[p].y += x.y; sacc[p].z += x.z; sacc[p].w += x.w;
            n2.x += x.x * x.x; n2.y += x.y * x.y; n2.z += x.z * x.z; n2.w += x.w * x.w;
        }
        float4 nb = make_float4(sqrtf(n2.x), sqrtf(n2.y), sqrtf(n2.z), sqrtf(n2.w));
        mx.x = fmaxf(mx.x, nb.x); mx.y = fmaxf(mx.y, nb.y);
        mx.z = fmaxf(mx.z, nb.z); mx.w = fmaxf(mx.w, nb.w);
        mn.x = fminf(mn.x, nb.x); mn.y = fminf(mn.y, nb.y);
        mn.z = fminf(mn.z, nb.z); mn.w = fminf(mn.w, nb.w);
    }

    int mi = (b * NC + c) * HW + hwoff;
    atomicMax(&g_maxb[mi + 0], __float_as_uint(mx.x));
    atomicMax(&g_maxb[mi + 1], __float_as_uint(mx.y));
    atomicMax(&g_maxb[mi + 2], __float_as_uint(mx.z));
    atomicMax(&g_maxb[mi + 3], __float_as_uint(mx.w));
    atomicMin(&g_minb[mi + 0], __float_as_uint(mn.x));
    atomicMin(&g_minb[mi + 1], __float_as_uint(mn.y));
    atomicMin(&g_minb[mi + 2], __float_as_uint(mn.z));
    atomicMin(&g_minb[mi + 3], __float_as_uint(mn.w));

    int sbase = ((b * NC + c) * NP) * HW + hwoff;
#pragma unroll
    for (int p = 0; p < NP; p++) {
        atomicAdd(&g_s[sbase + p * HW + 0], sacc[p].x);
        atomicAdd(&g_s[sbase + p * HW + 1], sacc[p].y);
        atomicAdd(&g_s[sbase + p * HW + 2], sacc[p].z);
        atomicAdd(&g_s[sbase + p * HW + 3], sacc[p].w);
    }
}

// ---------------------------------------------------------------------------
// squash: one thread per (b,C,hw4)
// mode 0: compute inv, scale=inv/32, g_v  = squash, zero g_s
// mode 1: scale=inv,                 g_v += squash, zero g_s   (linearity trick)
// mode 2: scale=inv,                 write v + a_out to output
__global__ void k_squash(float* __restrict__ vout, float* __restrict__ aout, int mode) {
    int i = blockIdx.x * blockDim.x + threadIdx.x;
    if (i >= NCHW4) return;
    int bc = i / 49, q4 = i % 49;
    int mi = bc * HW + q4 * 4;

    float inv[4];
    if (mode == 0) {
#pragma unroll
        for (int j = 0; j < 4; j++) {
            float mxv = __uint_as_float(g_maxb[mi + j]);
            float mnv = __uint_as_float(g_minb[mi + j]);
            inv[j] = 1.0f / (mxv - mnv);
            g_inv[mi + j] = inv[j];
        }
    } else {
        float4 iv = *(const float4*)&g_inv[mi];
        inv[0] = iv.x; inv[1] = iv.y; inv[2] = iv.z; inv[3] = iv.w;
    }
    float mul = (mode == 0) ? (1.0f / 32.0f) : 1.0f;
    float sc[4];
#pragma unroll
    for (int j = 0; j < 4; j++) sc[j] = inv[j] * mul;

    int sbase = bc * NP * HW + q4 * 4;
    float sv[NP][4];
    float n2[4] = {EPSF, EPSF, EPSF, EPSF};
#pragma unroll
    for (int p = 0; p < NP; p++) {
        float4 x = *(const float4*)&g_s[sbase + p * HW];
        float xs[4] = {x.x * sc[0], x.y * sc[1], x.z * sc[2], x.w * sc[3]};
#pragma unroll
        for (int j = 0; j < 4; j++) { sv[p][j] = xs[j]; n2[j] += xs[j] * xs[j]; }
    }
    float f[4];
#pragma unroll
    for (int j = 0; j < 4; j++) f[j] = 1.0f / (1.0f + sqrtf(n2[j]));

    if (mode < 2) {
#pragma unroll
        for (int p = 0; p < NP; p++) {
            float4 vold = make_float4(0.f, 0.f, 0.f, 0.f);
            if (mode == 1) vold = *(const float4*)&g_v[sbase + p * HW];
            float4 vn;
            vn.x = vold.x + sv[p][0] * f[0];
            vn.y = vold.y + sv[p][1] * f[1];
            vn.z = vold.z + sv[p][2] * f[2];
            vn.w = vold.w + sv[p][3] * f[3];
            *(float4*)&g_v[sbase + p * HW] = vn;
            *(float4*)&g_s[sbase + p * HW] = make_float4(0.f, 0.f, 0.f, 0.f);
        }
    } else {
        float av2[4] = {EPSF, EPSF, EPSF, EPSF};
#pragma unroll
        for (int p = 0; p < NP; p++) {
            float4 vn;
            vn.x = sv[p][0] * f[0]; vn.y = sv[p][1] * f[1];
            vn.z = sv[p][2] * f[2]; vn.w = sv[p][3] * f[3];
            *(float4*)&vout[sbase + p * HW] = vn;
            av2[0] += vn.x * vn.x; av2[1] += vn.y * vn.y;
            av2[2] += vn.z * vn.z; av2[3] += vn.w * vn.w;
        }
#pragma unroll
        for (int j = 0; j < 4; j++) aout[mi + j] = sqrtf(av2[j]);
    }
}

// ---------------------------------------------------------------------------
// Routing pass v4. grid (9 Bgroups of 32, 7 hw-chunks of 28, 4 b), 224 threads.
// thread = (c 0..31, q4 0..6): owns 1 C x ALL 16 P x 4 hw.
// r and exp(r) stay in registers; only exp values cross threads (1 STS.128);
// 28 reducer lanes compute 1/denom (32 scalar conflict-free LDS each).
// u in registers across softmax (single DRAM read); acc in registers.
#define RTH 224
extern __shared__ float sh[];

__global__ void __launch_bounds__(RTH, 1) k_route(const float* __restrict__ u) {
    float* v_sh    = sh;                       // NP*NC*VS = 30720 floats
    float* e_sh    = sh + NP * NC * VS;        // NC*36 = 1152
    float* dinv_sh = e_sh + NC * 36;           // 32

    int bg = blockIdx.x;   // 0..8
    int hq = blockIdx.y;   // 0..6
    int b  = blockIdx.z;   // 0..3
    int tid = threadIdx.x;
    int c  = tid / 7;             // 0..31
    int q4 = tid % 7;             // 0..6
    int hw0 = hq * 28;
    int hwoff = hw0 + q4 * 4;

    // load v: each thread loads its own (c,q4) column for all p
#pragma unroll
    for (int p = 0; p < NP; p++) {
        *(float4*)&v_sh[(p * NC + c) * VS + q4 * 4] =
            *(const float4*)&g_v[((b * NC + c) * NP + p) * HW + hwoff];
    }
    float4 invv = *(const float4*)&g_inv[(b * NC + c) * HW + hwoff];

    float4 acc[NP];
#pragma unroll
    for (int p = 0; p < NP; p++) acc[p] = make_float4(0.f, 0.f, 0.f, 0.f);

    const float* ub = u + (((size_t)(b * NB + bg * 32) * NC + c) * NP) * HW + hwoff;
    __syncthreads();

    for (int bi = 0; bi < 32; bi++) {
        const float* up = ub + (size_t)bi * (NC * NP * HW);
        float4 u4[NP];
#pragma unroll
        for (int p = 0; p < NP; p++) u4[p] = *(const float4*)(up + p * HW);

        // agreement r = inv * sum_P u.v  (all in registers)
        float4 r = make_float4(0.f, 0.f, 0.f, 0.f);
#pragma unroll
        for (int p = 0; p < NP; p++) {
            float4 vv = *(float4*)&v_sh[(p * NC + c) * VS + q4 * 4];
            r.x += u4[p].x * vv.x; r.y += u4[p].y * vv.y;
            r.z += u4[p].z * vv.z; r.w += u4[p].w * vv.w;
        }
        // softmax numerator (|r| small: safe without max subtraction)
        float4 e;
        e.x = __expf(r.x * invv.x); e.y = __expf(r.y * invv.y);
        e.z = __expf(r.z * invv.z); e.w = __expf(r.w * invv.w);
        *(float4*)&e_sh[c * 36 + q4 * 4] = e;
        __syncthreads();

        if (tid < 28) {
            float s = 0.f;
#pragma unroll
            for (int cc = 0; cc < NC; cc++) s += e_sh[cc * 36 + tid];
            dinv_sh[tid] = __frcp_rn(s);
        }
        __syncthreads();

        float4 d4 = *(float4*)&dinv_sh[q4 * 4];
        float4 cv;
        cv.x = e.x * d4.x; cv.y = e.y * d4.y;
        cv.z = e.z * d4.z; cv.w = e.w * d4.w;

        // s += c * u   (u still in registers)
#pragma unroll
        for (int p = 0; p < NP; p++) {
            acc[p].x += cv.x * u4[p].x; acc[p].y += cv.y * u4[p].y;
            acc[p].z += cv.z * u4[p].z; acc[p].w += cv.w * u4[p].w;
        }
    }

    int sbase = ((b * NC + c) * NP) * HW + hwoff;
#pragma unroll
    for (int p = 0; p < NP; p++) {
        atomicAdd(&g_s[sbase + p * HW + 0], acc[p].x);
        atomicAdd(&g_s[sbase + p * HW + 1], acc[p].y);
        atomicAdd(&g_s[sbase + p * HW + 2], acc[p].z);
        atomicAdd(&g_s[sbase + p * HW + 3], acc[p].w);
    }
}

// ---------------------------------------------------------------------------
extern "C" void kernel_launch(void* const* d_in, const int* in_sizes, int n_in,
                              void* d_out, int out_size) {
    const float* u = (const float*)d_in[0];   // (4,288,32,16,14,14)
    float* out  = (float*)d_out;
    float* vout = out;                        // (4,32,16,14,14)
    float* aout = out + NVPHW;                // (4,32,14,14)

    const int shbytes = (NP * NC * VS + NC * 36 + 32) * sizeof(float); // 127,616 B
    cudaFuncSetAttribute(k_route, cudaFuncAttributeMaxDynamicSharedMemorySize, shbytes);

    k_init<<<(NVPHW + 255) / 256, 256>>>();
    k_passA<<<dim3(9, 4, 4), 392>>>(u);
    k_squash<<<(NCHW4 + 255) / 256, 256>>>(nullptr, nullptr, 0);  // v0 = squash(s0)
    k_route<<<dim3(9, 7, 4), RTH, shbytes>>>(u);                  // s1 (uses v0)
    k_squash<<<(NCHW4 + 255) / 256, 256>>>(nullptr, nullptr, 1);  // g_v = v0+v1
    k_route<<<dim3(9, 7, 4), RTH, shbytes>>>(u);                  // s2 (uses v0+v1)
    k_squash<<<(NCHW4 + 255) / 256, 256>>>(vout, aout, 2);        // v2, a_out
}